// round 10
// baseline (speedup 1.0000x reference)
#include <cuda_runtime.h>
#include <cuda_bf16.h>
#include <stdint.h>

// ---------------------------------------------------------------------------
// GLCM layer, one kernel, angle-split:
//   out[b, a*64+code, py, px] =
//     (1/1024) * sum_{t in 36x36 ext. window} wy(i)*wx(j) *
//                [ code(reflect(t)) == code ]
// where code(s) = 8*gl(s) + gl(clamp(s + shift_a)), gl = ceil(x/32)-1.
//
// Each CTA handles one (batch, pool-cell, angle-group-of-4). Angle groups
// own disjoint output channels -> no cross-CTA reduction. Grid 256 x 512thr
// gives 2 co-resident CTAs/SM (grid=128 gave only 1), hiding barrier stalls.
// Tile is gathered with CLAMPED image coords so neighbor reads need no
// clamp: all shifted indices provably lie in [0,38).
// ---------------------------------------------------------------------------

#define H 256
#define W 256
#define NPIX (H * W)
#define NB 2
#define L2BINS 64
#define POOL 32
#define EXT 36          // 32 + 2*2 (box radius)
#define TILE 38         // 36 + 1-px shift halo (image coords [P0-3, P0+34])
#define TSTRIDE 40
#define NT 512
#define NW 16           // warps = per-warp histograms
#define NA 4            // angles per CTA
#define NBINS (NA * L2BINS)   // 256

__global__ __launch_bounds__(NT, 2)
void glcm_kernel(const float* __restrict__ x, float* __restrict__ out) {
    const int px = blockIdx.x;            // 0..7
    const int py = blockIdx.y;            // 0..7
    const int b  = blockIdx.z >> 1;       // 0..1
    const int ag = blockIdx.z & 1;        // angle group: 0 -> angles 0-3, 1 -> 4-7
    const int X0 = px * POOL;
    const int Y0 = py * POOL;
    const int tid = threadIdx.x;

    __shared__ int8_t tile[TILE * TSTRIDE];
    __shared__ int    hist[NW][NBINS];    // 16 x 256 ints = 16 KB

    // ---- issue all tile LDGs first, then zero hist while they're in flight
    const float* xb = x + b * NPIX;
    float v[3];
    int   rr[3], cc[3];
    #pragma unroll
    for (int k = 0; k < 3; k++) {
        int idx = tid + k * NT;
        rr[k] = idx / TILE; cc[k] = idx % TILE;
        if (idx < TILE * TILE) {
            int gy = min(max(Y0 - 3 + rr[k], 0), H - 1);
            int gx = min(max(X0 - 3 + cc[k], 0), W - 1);
            v[k] = xb[gy * W + gx];
        }
    }

    // zero histograms while LDGs are outstanding (2 int4 stores per thread)
    #pragma unroll
    for (int i = tid; i < NW * NBINS / 4; i += NT)
        ((int4*)hist)[i] = make_int4(0, 0, 0, 0);

    // quantize + store tile: gl = ceil(v/32) - 1 == searchsorted_left - 1
    #pragma unroll
    for (int k = 0; k < 3; k++) {
        int idx = tid + k * NT;
        if (idx < TILE * TILE)
            tile[rr[k] * TSTRIDE + cc[k]] =
                (int8_t)(__float2int_ru(v[k] * 0.03125f) - 1);
    }
    __syncthreads();

    int* whist = hist[tid >> 5];

    for (int pos = tid; pos < EXT * EXT; pos += NT) {
        int i = pos / EXT, j = pos % EXT;
        // separable triangular weights 1,2,3,4,5,...,5,4,3,2,1
        int wgt = min(min(i + 1, EXT - i), 5) * min(min(j + 1, EXT - j), 5);

        // reflect-pad mapping for the box-filter position
        int ty = Y0 - 2 + i; if (ty < 0) ty = -ty; else if (ty > H - 1) ty = 2 * (H - 1) - ty;
        int tx = X0 - 2 + j; if (tx < 0) tx = -tx; else if (tx > W - 1) tx = 2 * (W - 1) - tx;

        const int8_t* base = &tile[(ty - Y0 + 3) * TSTRIDE + (tx - X0 + 3)];
        int g1 = base[0];
        int g2[NA];
        if (ag == 0) {                       // angles 0..3
            g2[0] = base[1];                 // ( 1,  0)
            g2[1] = base[-TSTRIDE + 1];      // ( 1, -1)
            g2[2] = base[-TSTRIDE];          // ( 0, -1)
            g2[3] = base[-TSTRIDE - 1];      // (-1, -1)
        } else {                             // angles 4..7
            g2[0] = base[-1];                // (-1,  0)
            g2[1] = base[TSTRIDE - 1];       // (-1,  1)
            g2[2] = base[TSTRIDE];           // ( 0,  1)
            g2[3] = base[TSTRIDE + 1];       // ( 1,  1)
        }

        int c8 = g1 << 3;
        #pragma unroll
        for (int a = 0; a < NA; a++) {
            int code = c8 + g2[a];           // negative iff x==0 cases (reject)
            if ((unsigned)code < (unsigned)L2BINS)
                atomicAdd(&whist[a * L2BINS + code], wgt);
        }
    }
    __syncthreads();

    // reduce 16 histograms; write this CTA's disjoint output slice
    const float inv = 1.0f / (float)(POOL * POOL);
    if (tid < NBINS) {
        int s = 0;
        #pragma unroll
        for (int wp = 0; wp < NW; wp++) s += hist[wp][tid];
        int ch = ag * NBINS + tid;           // global channel in [0,512)
        out[((b * 512 + ch) * 8 + py) * 8 + px] = (float)s * inv;
    }
}

extern "C" void kernel_launch(void* const* d_in, const int* in_sizes, int n_in,
                              void* d_out, int out_size) {
    const float* x = (const float*)d_in[0];
    float* out = (float*)d_out;
    dim3 grid(8, 8, NB * 2);
    glcm_kernel<<<grid, NT>>>(x, out);
}